// round 12
// baseline (speedup 1.0000x reference)
#include <cuda_runtime.h>
#include <cuda_bf16.h>
#include <math.h>
#include <stdint.h>

// ExamplarLoss fused, symmetric, balanced single-wave schedule (R8 structure):
// prep kernel (normalize -> bf16*sqrt(log2e), fp32 pos, zero rowsums), then
// sim kernel: 2080 upper-tri 128x128 HMMA tiles in 296 strips (8x8 + 288x7),
// B double-buffered cp.async, fused sum-of-exp2 epilogue, dual-sided accum.
// Finalize runs in-kernel on the last CTA but inside a __noinline__ function
// so its register demand cannot perturb the mainloop's allocation (R11 bug).

#define NN 8192
#define DD 128
#define NB 64
#define NSTRIPS 296

__device__ uint4  g_bf4[NN * DD / 8];   // normalized*sqrt(log2e) rows, bf16 (2 MB)
__device__ float  g_rowsum[NN];         // per-row sum of exp2 (atomic accum)
__device__ float  g_pos[NN];            // fp32 cosine of positive pair
__device__ int    g_ctadone;            // finalize election; reset by last CTA

#define SQRT_LOG2E 1.2011224087864498f
#define E_CONST    2.718281828459045f

// ------------------------- PTX helpers (base ISA) -------------------------
__device__ __forceinline__ uint32_t smem_u32(const void* p) {
    uint32_t a;
    asm("{ .reg .u64 t; cvta.to.shared.u64 t, %1; cvt.u32.u64 %0, t; }" : "=r"(a) : "l"(p));
    return a;
}
__device__ __forceinline__ void cp16(uint32_t dst, const void* src) {
    asm volatile("cp.async.cg.shared.global [%0], [%1], 16;" :: "r"(dst), "l"(src));
}
#define CP_COMMIT() asm volatile("cp.async.commit_group;" ::: "memory")
#define CP_WAIT1()  asm volatile("cp.async.wait_group 1;" ::: "memory")

__device__ __forceinline__ void ldsm4(uint32_t (&r)[4], uint32_t addr) {
    asm volatile("ldmatrix.sync.aligned.m8n8.x4.shared.b16 {%0,%1,%2,%3}, [%4];"
                 : "=r"(r[0]), "=r"(r[1]), "=r"(r[2]), "=r"(r[3]) : "r"(addr));
}
__device__ __forceinline__ void mma16816(float (&d)[4], const uint32_t (&a)[4],
                                         const uint32_t* b) {
    asm volatile("mma.sync.aligned.m16n8k16.row.col.f32.bf16.bf16.f32 "
                 "{%0,%1,%2,%3}, {%4,%5,%6,%7}, {%8,%9}, {%0,%1,%2,%3};"
                 : "+f"(d[0]), "+f"(d[1]), "+f"(d[2]), "+f"(d[3])
                 : "r"(a[0]), "r"(a[1]), "r"(a[2]), "r"(a[3]), "r"(b[0]), "r"(b[1]));
}

// ---------------- Phase 1: normalize + pos; zero accumulators --------------
__global__ void __launch_bounds__(256) prep_kernel(const float* __restrict__ l1,
                                                   const float* __restrict__ l2) {
    const int tid = threadIdx.x;
    const int q = blockIdx.x * 8 + (tid >> 5);
    const int lane = tid & 31;
    if (tid < 32) g_rowsum[blockIdx.x * 32 + tid] = 0.f;

    const int pA = 2 * q, pB = 2 * q + 1;
    const float4 a1 = ((const float4*)(l1 + (size_t)pA * DD))[lane];
    const float4 a2 = ((const float4*)(l2 + (size_t)pA * DD))[lane];
    const float4 b1 = ((const float4*)(l1 + (size_t)pB * DD))[lane];
    const float4 b2 = ((const float4*)(l2 + (size_t)pB * DD))[lane];

    float sa1 = a1.x * a1.x + a1.y * a1.y + a1.z * a1.z + a1.w * a1.w;
    float sa2 = a2.x * a2.x + a2.y * a2.y + a2.z * a2.z + a2.w * a2.w;
    float da  = a1.x * a2.x + a1.y * a2.y + a1.z * a2.z + a1.w * a2.w;
    float sb1 = b1.x * b1.x + b1.y * b1.y + b1.z * b1.z + b1.w * b1.w;
    float sb2 = b2.x * b2.x + b2.y * b2.y + b2.z * b2.z + b2.w * b2.w;
    float db  = b1.x * b2.x + b1.y * b2.y + b1.z * b2.z + b1.w * b2.w;
    #pragma unroll
    for (int o = 16; o; o >>= 1) {
        sa1 += __shfl_xor_sync(0xffffffffu, sa1, o);
        sa2 += __shfl_xor_sync(0xffffffffu, sa2, o);
        da  += __shfl_xor_sync(0xffffffffu, da, o);
        sb1 += __shfl_xor_sync(0xffffffffu, sb1, o);
        sb2 += __shfl_xor_sync(0xffffffffu, sb2, o);
        db  += __shfl_xor_sync(0xffffffffu, db, o);
    }
    const float ia1 = rsqrtf(sa1), ia2 = rsqrtf(sa2);
    const float ib1 = rsqrtf(sb1), ib2 = rsqrtf(sb2);

    #pragma unroll
    for (int r = 0; r < 4; r++) {
        const float4 v = (r == 0) ? a1 : (r == 1) ? a2 : (r == 2) ? b1 : b2;
        const float c = ((r == 0) ? ia1 : (r == 1) ? ia2 : (r == 2) ? ib1 : ib2) * SQRT_LOG2E;
        __nv_bfloat162 p0 = __floats2bfloat162_rn(v.x * c, v.y * c);
        __nv_bfloat162 p1 = __floats2bfloat162_rn(v.z * c, v.w * c);
        uint2 pk;
        pk.x = *(uint32_t*)&p0;
        pk.y = *(uint32_t*)&p1;
        ((uint2*)g_bf4)[(size_t)(4 * q + r) * 32 + lane] = pk;
    }
    if (lane == 0) {
        const float posA = da * ia1 * ia2;
        const float posB = db * ib1 * ib2;
        g_pos[4 * q + 0] = posA;
        g_pos[4 * q + 1] = posA;
        g_pos[4 * q + 2] = posB;
        g_pos[4 * q + 3] = posB;
    }
}

// ---------------- finalize (register-isolated from the mainloop) -----------
__device__ __noinline__ void finalize_loss(float* __restrict__ out, int tid) {
    __shared__ float ws[8];
    float acc = 0.f;
    #pragma unroll 4
    for (int i = tid; i < NN; i += 256)
        acc += logf(g_rowsum[i] + 1.f - E_CONST) - g_pos[i];
    #pragma unroll
    for (int o = 16; o; o >>= 1) acc += __shfl_xor_sync(0xffffffffu, acc, o);
    if ((tid & 31) == 0) ws[tid >> 5] = acc;
    __syncthreads();
    if (tid < 8) {
        float r = ws[tid];
        #pragma unroll
        for (int o = 4; o; o >>= 1) r += __shfl_xor_sync(0x000000ffu, r, o);
        if (tid == 0) {
            out[0] = r * (1.f / (float)NN);
            g_ctadone = 0;           // reset for next graph replay
        }
    }
}

// ---------------- Phase 2: balanced symmetric HMMA + fused sum-exp2 --------
// SMEM: A 32KB | B buf0 32KB | B buf1 32KB
#define S_A    0
#define S_B    32768
#define S_TOT  98304

__device__ __forceinline__ void load_tile(uint32_t dst, int blk, int tid) {
    const char* src = (const char*)g_bf4 + (size_t)blk * 128 * 256;
    #pragma unroll
    for (int jj = 0; jj < 8; jj++) {
        const int idx = jj * 256 + tid, r = idx >> 4, c = idx & 15;
        cp16(dst + (uint32_t)(r * 256 + ((c ^ (r & 7)) << 4)), src + idx * 16);
    }
}

__global__ void __launch_bounds__(256, 2) sim_kernel(float* __restrict__ out) {
    extern __shared__ char sm[];
    const uint32_t sb = smem_u32(sm);
    const int tid = threadIdx.x;
    const int w = tid >> 5, l = tid & 31;
    const int rw = w >> 1, cw = w & 1;

    const int bid = blockIdx.x;
    int off, len;
    if (bid < 8) { off = bid * 8; len = 8; }
    else         { off = 64 + (bid - 8) * 7; len = 7; }

    int ib = 0;
    while (64 * (ib + 1) - ((ib + 1) * ib) / 2 <= off) ib++;
    int jb = ib + (off - (64 * ib - (ib * (ib - 1)) / 2));

    load_tile(sb + S_A, ib, tid);
    load_tile(sb + S_B, jb, tid);
    CP_COMMIT();
    int ibn = ib, jbn = jb;
    { jbn++; if (jbn == NB) { ibn++; jbn = ibn; } }
    load_tile(sb + S_B + 32768, jbn, tid);
    CP_COMMIT();
    CP_WAIT1();
    __syncthreads();

    uint32_t aBase[2], bRel[4];
    #pragma unroll
    for (int mf = 0; mf < 2; mf++)
        aBase[mf] = sb + S_A + (uint32_t)((rw * 32 + mf * 16 + (l & 15)) * 256);
    const int bn = (l & 7) + ((l >> 4) << 3);
    #pragma unroll
    for (int nf2 = 0; nf2 < 4; nf2++)
        bRel[nf2] = (uint32_t)((cw * 64 + nf2 * 16 + bn) * 256);
    const int akc = l >> 4;
    const int bkc = (l >> 3) & 1;
    const int sxor = l & 7;

    float rpart[2][2] = {{0.f, 0.f}, {0.f, 0.f}};
    int ibc = ib, jbc = jb;

    #pragma unroll 1
    for (int t = 0; t < len; t++) {
        const bool diag = (ibc == jbc);
        const uint32_t bb = sb + S_B + (uint32_t)((t & 1) * 32768);

        float acc[2][8][4];
        #pragma unroll
        for (int mf = 0; mf < 2; mf++)
            #pragma unroll
            for (int nf = 0; nf < 8; nf++)
                #pragma unroll
                for (int e = 0; e < 4; e++) acc[mf][nf][e] = 0.f;

        #pragma unroll
        for (int k = 0; k < 8; k++) {
            uint32_t a[2][4], b[4][4];
            #pragma unroll
            for (int mf = 0; mf < 2; mf++)
                ldsm4(a[mf], aBase[mf] + (((k * 2 + akc) ^ sxor) << 4));
            #pragma unroll
            for (int nf2 = 0; nf2 < 4; nf2++)
                ldsm4(b[nf2], bb + bRel[nf2] + (((k * 2 + bkc) ^ sxor) << 4));
            #pragma unroll
            for (int mf = 0; mf < 2; mf++)
                #pragma unroll
                for (int nf = 0; nf < 8; nf++)
                    mma16816(acc[mf][nf], a[mf], &b[nf >> 1][(nf & 1) * 2]);
        }

        float cpart[8][2];
        #pragma unroll
        for (int nf = 0; nf < 8; nf++) { cpart[nf][0] = 0.f; cpart[nf][1] = 0.f; }
        #pragma unroll
        for (int mf = 0; mf < 2; mf++)
            #pragma unroll
            for (int nf = 0; nf < 8; nf++) {
                const float e0 = exp2f(acc[mf][nf][0]);
                const float e1 = exp2f(acc[mf][nf][1]);
                const float e2 = exp2f(acc[mf][nf][2]);
                const float e3 = exp2f(acc[mf][nf][3]);
                rpart[mf][0] += e0 + e1;
                rpart[mf][1] += e2 + e3;
                cpart[nf][0] += e0 + e2;
                cpart[nf][1] += e1 + e3;
            }
        if (!diag) {
            #pragma unroll
            for (int o = 4; o <= 16; o <<= 1)
                #pragma unroll
                for (int nf = 0; nf < 8; nf++)
                    #pragma unroll
                    for (int pp = 0; pp < 2; pp++)
                        cpart[nf][pp] += __shfl_xor_sync(0xffffffffu, cpart[nf][pp], o);
            if (l < 4) {
                #pragma unroll
                for (int nf = 0; nf < 8; nf++)
                    #pragma unroll
                    for (int pp = 0; pp < 2; pp++)
                        atomicAdd(&g_rowsum[jbc * 128 + cw * 64 + nf * 8 + l * 2 + pp],
                                  cpart[nf][pp]);
            }
        }

        __syncthreads();

        const bool last = (t == len - 1);
        const bool achange = !last && (ibn != ibc);

        if (achange) {
            load_tile(sb + S_A, ibn, tid);
            CP_COMMIT();
        }
        if (t + 2 < len) {
            int ib2 = ibn, jb2 = jbn;
            { jb2++; if (jb2 == NB) { ib2++; jb2 = ib2; } }
            load_tile(sb + S_B + (uint32_t)((t & 1) * 32768), jb2, tid);
        }
        CP_COMMIT();

        if (achange || last) {
            float rp[2][2] = {{rpart[0][0], rpart[0][1]}, {rpart[1][0], rpart[1][1]}};
            #pragma unroll
            for (int o = 1; o <= 2; o <<= 1)
                #pragma unroll
                for (int mf = 0; mf < 2; mf++)
                    #pragma unroll
                    for (int h = 0; h < 2; h++)
                        rp[mf][h] += __shfl_xor_sync(0xffffffffu, rp[mf][h], o);
            if ((l & 3) == 0) {
                #pragma unroll
                for (int mf = 0; mf < 2; mf++)
                    #pragma unroll
                    for (int h = 0; h < 2; h++)
                        atomicAdd(&g_rowsum[ibc * 128 + rw * 32 + mf * 16 + h * 8 + (l >> 2)],
                                  rp[mf][h]);
            }
            rpart[0][0] = rpart[0][1] = rpart[1][0] = rpart[1][1] = 0.f;
        }

        if (!last) {
            CP_WAIT1();
            __syncthreads();
            ibc = ibn; jbc = jbn;
            { jbn++; if (jbn == NB) { ibn++; jbn = ibn; } }
        }
    }

    // ---------------- election + register-isolated finalize ----------------
    __shared__ int s_last;
    __threadfence();                 // release: rowsum atomics visible chip-wide
    __syncthreads();
    if (tid == 0) s_last = (atomicAdd(&g_ctadone, 1) == NSTRIPS - 1) ? 1 : 0;
    __syncthreads();
    if (s_last) {
        __threadfence();             // acquire
        finalize_loss(out, tid);
    }
}

extern "C" void kernel_launch(void* const* d_in, const int* in_sizes, int n_in,
                              void* d_out, int out_size) {
    const float* l1 = (const float*)d_in[0];
    const float* l2 = (const float*)d_in[1];
    float* out = (float*)d_out;

    cudaFuncSetAttribute(sim_kernel, cudaFuncAttributeMaxDynamicSharedMemorySize, S_TOT);

    prep_kernel<<<256, 256>>>(l1, l2);
    sim_kernel<<<NSTRIPS, 256, S_TOT>>>(out);
}

// round 13
// speedup vs baseline: 1.2646x; 1.2646x over previous
#include <cuda_runtime.h>
#include <cuda_bf16.h>
#include <math.h>
#include <stdint.h>

// ExamplarLoss fused, symmetric, balanced single-wave schedule (R8 structure,
// 3 kernels -- in-kernel finalize abandoned: any extra register pressure in
// sim_kernel causes mainloop spills at the 128-reg/2-CTA boundary).
// prep: one warp per pair (4096 warps) -> double MLP vs R8, ~3.5us.
// sim:  2080 upper-tri 128x128 HMMA tiles in 296 strips (8x8 + 288x7),
//       B double-buffered cp.async, fused sum-of-exp2 epilogue, dual-sided.
// finrow: per-row log + pos subtraction, block-reduce, atomicAdd into out.

#define NN 8192
#define DD 128
#define NB 64
#define NSTRIPS 296

__device__ uint4  g_bf4[NN * DD / 8];   // normalized*sqrt(log2e) rows, bf16 (2 MB)
__device__ float  g_rowsum[NN];         // per-row sum of exp2 (atomic accum)
__device__ float  g_pos[NN];            // fp32 cosine of positive pair

#define SQRT_LOG2E 1.2011224087864498f
#define E_CONST    2.718281828459045f

// ------------------------- PTX helpers (base ISA) -------------------------
__device__ __forceinline__ uint32_t smem_u32(const void* p) {
    uint32_t a;
    asm("{ .reg .u64 t; cvta.to.shared.u64 t, %1; cvt.u32.u64 %0, t; }" : "=r"(a) : "l"(p));
    return a;
}
__device__ __forceinline__ void cp16(uint32_t dst, const void* src) {
    asm volatile("cp.async.cg.shared.global [%0], [%1], 16;" :: "r"(dst), "l"(src));
}
#define CP_COMMIT() asm volatile("cp.async.commit_group;" ::: "memory")
#define CP_WAIT1()  asm volatile("cp.async.wait_group 1;" ::: "memory")

__device__ __forceinline__ void ldsm4(uint32_t (&r)[4], uint32_t addr) {
    asm volatile("ldmatrix.sync.aligned.m8n8.x4.shared.b16 {%0,%1,%2,%3}, [%4];"
                 : "=r"(r[0]), "=r"(r[1]), "=r"(r[2]), "=r"(r[3]) : "r"(addr));
}
__device__ __forceinline__ void mma16816(float (&d)[4], const uint32_t (&a)[4],
                                         const uint32_t* b) {
    asm volatile("mma.sync.aligned.m16n8k16.row.col.f32.bf16.bf16.f32 "
                 "{%0,%1,%2,%3}, {%4,%5,%6,%7}, {%8,%9}, {%0,%1,%2,%3};"
                 : "+f"(d[0]), "+f"(d[1]), "+f"(d[2]), "+f"(d[3])
                 : "r"(a[0]), "r"(a[1]), "r"(a[2]), "r"(a[3]), "r"(b[0]), "r"(b[1]));
}

// ---------------- Phase 1: normalize + pos; zero accumulators --------------
// One warp per pair (rows 2q from l1, 2q+1 from l2): 4096 warps, grid 512.
__global__ void __launch_bounds__(256) prep_kernel(const float* __restrict__ l1,
                                                   const float* __restrict__ l2,
                                                   float* __restrict__ out) {
    const int tid = threadIdx.x;
    const int q = blockIdx.x * 8 + (tid >> 5);   // pair id, 0..4095
    const int lane = tid & 31;
    if (tid < 16) g_rowsum[blockIdx.x * 16 + tid] = 0.f;
    if (blockIdx.x == 0 && tid == 0) out[0] = 0.f;

    const float4 v1 = ((const float4*)(l1 + (size_t)q * DD))[lane];
    const float4 v2 = ((const float4*)(l2 + (size_t)q * DD))[lane];
    float s1 = v1.x * v1.x + v1.y * v1.y + v1.z * v1.z + v1.w * v1.w;
    float s2 = v2.x * v2.x + v2.y * v2.y + v2.z * v2.z + v2.w * v2.w;
    float dt = v1.x * v2.x + v1.y * v2.y + v1.z * v2.z + v1.w * v2.w;
    #pragma unroll
    for (int o = 16; o; o >>= 1) {
        s1 += __shfl_xor_sync(0xffffffffu, s1, o);
        s2 += __shfl_xor_sync(0xffffffffu, s2, o);
        dt += __shfl_xor_sync(0xffffffffu, dt, o);
    }
    const float i1 = rsqrtf(s1), i2 = rsqrtf(s2);
    const float c1 = i1 * SQRT_LOG2E, c2 = i2 * SQRT_LOG2E;

    __nv_bfloat162 a0 = __floats2bfloat162_rn(v1.x * c1, v1.y * c1);
    __nv_bfloat162 a1 = __floats2bfloat162_rn(v1.z * c1, v1.w * c1);
    __nv_bfloat162 b0 = __floats2bfloat162_rn(v2.x * c2, v2.y * c2);
    __nv_bfloat162 b1 = __floats2bfloat162_rn(v2.z * c2, v2.w * c2);
    uint2 pk1, pk2;
    pk1.x = *(uint32_t*)&a0; pk1.y = *(uint32_t*)&a1;
    pk2.x = *(uint32_t*)&b0; pk2.y = *(uint32_t*)&b1;
    ((uint2*)g_bf4)[(size_t)(2 * q) * 32 + lane] = pk1;
    ((uint2*)g_bf4)[(size_t)(2 * q + 1) * 32 + lane] = pk2;

    if (lane == 0) {
        const float pos = dt * i1 * i2;
        g_pos[2 * q] = pos;
        g_pos[2 * q + 1] = pos;
    }
}

// ---------------- Phase 2: balanced symmetric HMMA + fused sum-exp2 --------
// SMEM: A 32KB | B buf0 32KB | B buf1 32KB
#define S_A    0
#define S_B    32768
#define S_TOT  98304

__device__ __forceinline__ void load_tile(uint32_t dst, int blk, int tid) {
    const char* src = (const char*)g_bf4 + (size_t)blk * 128 * 256;
    #pragma unroll
    for (int jj = 0; jj < 8; jj++) {
        const int idx = jj * 256 + tid, r = idx >> 4, c = idx & 15;
        cp16(dst + (uint32_t)(r * 256 + ((c ^ (r & 7)) << 4)), src + idx * 16);
    }
}

__global__ void __launch_bounds__(256, 2) sim_kernel() {
    extern __shared__ char sm[];
    const uint32_t sb = smem_u32(sm);
    const int tid = threadIdx.x;
    const int w = tid >> 5, l = tid & 31;
    const int rw = w >> 1, cw = w & 1;

    // strip: first 8 CTAs take 8 tiles each (row 0), rest take 7
    const int bid = blockIdx.x;
    int off, len;
    if (bid < 8) { off = bid * 8; len = 8; }
    else         { off = 64 + (bid - 8) * 7; len = 7; }

    int ib = 0;
    while (64 * (ib + 1) - ((ib + 1) * ib) / 2 <= off) ib++;
    int jb = ib + (off - (64 * ib - (ib * (ib - 1)) / 2));

    load_tile(sb + S_A, ib, tid);
    load_tile(sb + S_B, jb, tid);
    CP_COMMIT();
    int ibn = ib, jbn = jb;
    { jbn++; if (jbn == NB) { ibn++; jbn = ibn; } }
    load_tile(sb + S_B + 32768, jbn, tid);
    CP_COMMIT();
    CP_WAIT1();
    __syncthreads();

    uint32_t aBase[2], bRel[4];
    #pragma unroll
    for (int mf = 0; mf < 2; mf++)
        aBase[mf] = sb + S_A + (uint32_t)((rw * 32 + mf * 16 + (l & 15)) * 256);
    const int bn = (l & 7) + ((l >> 4) << 3);
    #pragma unroll
    for (int nf2 = 0; nf2 < 4; nf2++)
        bRel[nf2] = (uint32_t)((cw * 64 + nf2 * 16 + bn) * 256);
    const int akc = l >> 4;
    const int bkc = (l >> 3) & 1;
    const int sxor = l & 7;

    float rpart[2][2] = {{0.f, 0.f}, {0.f, 0.f}};
    int ibc = ib, jbc = jb;

    #pragma unroll 1
    for (int t = 0; t < len; t++) {
        const bool diag = (ibc == jbc);
        const uint32_t bb = sb + S_B + (uint32_t)((t & 1) * 32768);

        float acc[2][8][4];
        #pragma unroll
        for (int mf = 0; mf < 2; mf++)
            #pragma unroll
            for (int nf = 0; nf < 8; nf++)
                #pragma unroll
                for (int e = 0; e < 4; e++) acc[mf][nf][e] = 0.f;

        #pragma unroll
        for (int k = 0; k < 8; k++) {
            uint32_t a[2][4], b[4][4];
            #pragma unroll
            for (int mf = 0; mf < 2; mf++)
                ldsm4(a[mf], aBase[mf] + (((k * 2 + akc) ^ sxor) << 4));
            #pragma unroll
            for (int nf2 = 0; nf2 < 4; nf2++)
                ldsm4(b[nf2], bb + bRel[nf2] + (((k * 2 + bkc) ^ sxor) << 4));
            #pragma unroll
            for (int mf = 0; mf < 2; mf++)
                #pragma unroll
                for (int nf = 0; nf < 8; nf++)
                    mma16816(acc[mf][nf], a[mf], &b[nf >> 1][(nf & 1) * 2]);
        }

        float cpart[8][2];
        #pragma unroll
        for (int nf = 0; nf < 8; nf++) { cpart[nf][0] = 0.f; cpart[nf][1] = 0.f; }
        #pragma unroll
        for (int mf = 0; mf < 2; mf++)
            #pragma unroll
            for (int nf = 0; nf < 8; nf++) {
                const float e0 = exp2f(acc[mf][nf][0]);
                const float e1 = exp2f(acc[mf][nf][1]);
                const float e2 = exp2f(acc[mf][nf][2]);
                const float e3 = exp2f(acc[mf][nf][3]);
                rpart[mf][0] += e0 + e1;
                rpart[mf][1] += e2 + e3;
                cpart[nf][0] += e0 + e2;
                cpart[nf][1] += e1 + e3;
            }
        if (!diag) {
            #pragma unroll
            for (int o = 4; o <= 16; o <<= 1)
                #pragma unroll
                for (int nf = 0; nf < 8; nf++)
                    #pragma unroll
                    for (int pp = 0; pp < 2; pp++)
                        cpart[nf][pp] += __shfl_xor_sync(0xffffffffu, cpart[nf][pp], o);
            if (l < 4) {
                #pragma unroll
                for (int nf = 0; nf < 8; nf++)
                    #pragma unroll
                    for (int pp = 0; pp < 2; pp++)
                        atomicAdd(&g_rowsum[jbc * 128 + cw * 64 + nf * 8 + l * 2 + pp],
                                  cpart[nf][pp]);
            }
        }

        __syncthreads();

        const bool last = (t == len - 1);
        const bool achange = !last && (ibn != ibc);

        if (achange) {
            load_tile(sb + S_A, ibn, tid);
            CP_COMMIT();
        }
        if (t + 2 < len) {
            int ib2 = ibn, jb2 = jbn;
            { jb2++; if (jb2 == NB) { ib2++; jb2 = ib2; } }
            load_tile(sb + S_B + (uint32_t)((t & 1) * 32768), jb2, tid);
        }
        CP_COMMIT();

        if (achange || last) {
            float rp[2][2] = {{rpart[0][0], rpart[0][1]}, {rpart[1][0], rpart[1][1]}};
            #pragma unroll
            for (int o = 1; o <= 2; o <<= 1)
                #pragma unroll
                for (int mf = 0; mf < 2; mf++)
                    #pragma unroll
                    for (int h = 0; h < 2; h++)
                        rp[mf][h] += __shfl_xor_sync(0xffffffffu, rp[mf][h], o);
            if ((l & 3) == 0) {
                #pragma unroll
                for (int mf = 0; mf < 2; mf++)
                    #pragma unroll
                    for (int h = 0; h < 2; h++)
                        atomicAdd(&g_rowsum[ibc * 128 + rw * 32 + mf * 16 + h * 8 + (l >> 2)],
                                  rp[mf][h]);
            }
            rpart[0][0] = rpart[0][1] = rpart[1][0] = rpart[1][1] = 0.f;
        }

        if (!last) {
            CP_WAIT1();
            __syncthreads();
            ibc = ibn; jbc = jbn;
            { jbn++; if (jbn == NB) { ibn++; jbn = ibn; } }
        }
    }
}

// ---------------- Phase 3: per-row contrib, block-reduce, atomic into out --
__global__ void __launch_bounds__(256) finrow_kernel(float* __restrict__ out) {
    __shared__ float ws[8];
    const int i = blockIdx.x * 256 + threadIdx.x;
    // rowsum includes exp2(sii) ~= e on the diagonal; reference wants exp(0)=1
    float contrib = logf(g_rowsum[i] + 1.f - E_CONST) - g_pos[i];
    #pragma unroll
    for (int o = 16; o; o >>= 1) contrib += __shfl_xor_sync(0xffffffffu, contrib, o);
    if ((threadIdx.x & 31) == 0) ws[threadIdx.x >> 5] = contrib;
    __syncthreads();
    if (threadIdx.x < 8) {
        float acc = ws[threadIdx.x];
        #pragma unroll
        for (int o = 4; o; o >>= 1) acc += __shfl_xor_sync(0x000000ffu, acc, o);
        if (threadIdx.x == 0) atomicAdd(out, acc * (1.f / (float)NN));
    }
}

extern "C" void kernel_launch(void* const* d_in, const int* in_sizes, int n_in,
                              void* d_out, int out_size) {
    const float* l1 = (const float*)d_in[0];
    const float* l2 = (const float*)d_in[1];
    float* out = (float*)d_out;

    cudaFuncSetAttribute(sim_kernel, cudaFuncAttributeMaxDynamicSharedMemorySize, S_TOT);

    prep_kernel<<<512, 256>>>(l1, l2, out);     // one warp per pair
    sim_kernel<<<NSTRIPS, 256, S_TOT>>>();
    finrow_kernel<<<NN / 256, 256>>>(out);
}